// round 1
// baseline (speedup 1.0000x reference)
#include <cuda_runtime.h>
#include <math_constants.h>
#include <math.h>

// ---------------------------------------------------------------------------
// Problem constants
// ---------------------------------------------------------------------------
namespace {
constexpr int kD  = 1024;
constexpr int kH  = 8;
constexpr int kDH = 128;
constexpr int kFF = 2048;
constexpr int kL  = 3;
constexpr int kB  = 8;
constexpr int kT  = 256;
constexpr int kU  = 1024;
constexpr int kTextV = 128257;
constexpr int kUnitV = 10001;
constexpr float kLnEps = 1e-5f;
constexpr float kTemp  = 0.0005f;
constexpr float kNeg   = -1e9f;
constexpr float kScale = 0.08838834764831845f;  // 1/sqrt(128)
}

// ---------------------------------------------------------------------------
// Scratch (device globals; no allocations allowed)
// ---------------------------------------------------------------------------
__device__ float g_x_u[kB * kU * kD];                 // 32 MB
__device__ float g_x_t[kB * kT * kD];                 // 8 MB
__device__ float g_qkv[kB * kU * 3 * kD];             // 96 MB
__device__ float g_scores[(size_t)kB * kH * kU * kU]; // 256 MB
__device__ float g_att[kB * kU * kD];                 // 32 MB
__device__ float g_ffb[kB * kU * kFF];                // 64 MB
__device__ float g_un[kB * kU];
__device__ float g_tn[kB * kT];
__device__ int   g_pad_u[kB * kU];
__device__ int   g_pad_t[kB * kT];

// ---------------------------------------------------------------------------
// Reduction helpers (blockDim.x == 256 assumed everywhere)
// ---------------------------------------------------------------------------
__device__ __forceinline__ float warp_sum(float v) {
#pragma unroll
    for (int o = 16; o > 0; o >>= 1) v += __shfl_xor_sync(0xffffffffu, v, o);
    return v;
}
__device__ __forceinline__ float warp_max(float v) {
#pragma unroll
    for (int o = 16; o > 0; o >>= 1) v = fmaxf(v, __shfl_xor_sync(0xffffffffu, v, o));
    return v;
}
__device__ __forceinline__ float block_sum(float v, float* sh) {
    v = warp_sum(v);
    if ((threadIdx.x & 31) == 0) sh[threadIdx.x >> 5] = v;
    __syncthreads();
    float r = 0.f;
#pragma unroll
    for (int i = 0; i < 8; i++) r += sh[i];
    __syncthreads();
    return r;
}
__device__ __forceinline__ float block_max(float v, float* sh) {
    v = warp_max(v);
    if ((threadIdx.x & 31) == 0) sh[threadIdx.x >> 5] = v;
    __syncthreads();
    float r = -CUDART_INF_F;
#pragma unroll
    for (int i = 0; i < 8; i++) r = fmaxf(r, sh[i]);
    __syncthreads();
    return r;
}

// ---------------------------------------------------------------------------
// Generic fp32 GEMM:  C = act(A @ op(B) + bias)
//   TRANSB: B is [N,K] row-major (C = A * B^T); else B is [K,N] row-major.
// Batched via blockIdx.z, decomposed as z = zo*innerB + zi with separate
// outer/inner element strides per operand (covers per-(b,h) attention GEMMs).
// REQUIRES: M % 64 == 0, N % 64 == 0, K % 16 == 0 (true for all call sites).
// Tile 64x64x16, 256 threads, 4x4 micro-tile per thread.
// ---------------------------------------------------------------------------
template <bool TRANSB, bool RELU>
__global__ void __launch_bounds__(256)
gemm64_kernel(const float* __restrict__ A, const float* __restrict__ B,
              const float* __restrict__ bias, float* __restrict__ C,
              int M, int N, int K, int lda, int ldb, int ldc,
              int innerB,
              long long sAo, long long sAi, long long sBo, long long sBi,
              long long sCo, long long sCi)
{
    const int z  = blockIdx.z;
    const int zo = z / innerB;
    const int zi = z - zo * innerB;
    A += zo * sAo + zi * sAi;
    B += zo * sBo + zi * sBi;
    C += zo * sCo + zi * sCi;

    const int m0 = blockIdx.y * 64;
    const int n0 = blockIdx.x * 64;
    const int tid = threadIdx.x;
    const int tx = tid & 15;       // 0..15 (col group)
    const int ty = tid >> 4;       // 0..15 (row group)

    __shared__ float As[16][68];
    __shared__ float Bs[16][68];

    float acc[4][4] = {};

    const int am = tid >> 2;   // 0..63 row of A tile
    const int af = tid & 3;    // which float4 in the 16-wide K chunk
    const int bn = tid & 15;   // for !TRANSB
    const int bk = tid >> 4;

    for (int kt = 0; kt < K; kt += 16) {
        // load A tile (64 rows x 16 k), transposed into As[k][m]
        {
            float4 a4 = *(const float4*)(A + (long long)(m0 + am) * lda + (kt + af * 4));
            As[af * 4 + 0][am] = a4.x;
            As[af * 4 + 1][am] = a4.y;
            As[af * 4 + 2][am] = a4.z;
            As[af * 4 + 3][am] = a4.w;
        }
        if (TRANSB) {
            float4 b4 = *(const float4*)(B + (long long)(n0 + am) * ldb + (kt + af * 4));
            Bs[af * 4 + 0][am] = b4.x;
            Bs[af * 4 + 1][am] = b4.y;
            Bs[af * 4 + 2][am] = b4.z;
            Bs[af * 4 + 3][am] = b4.w;
        } else {
            float4 b4 = *(const float4*)(B + (long long)(kt + bk) * ldb + (n0 + bn * 4));
            *(float4*)&Bs[bk][bn * 4] = b4;
        }
        __syncthreads();

#pragma unroll
        for (int k = 0; k < 16; k++) {
            float4 av = *(const float4*)&As[k][ty * 4];
            float4 bv = *(const float4*)&Bs[k][tx * 4];
            acc[0][0] += av.x * bv.x; acc[0][1] += av.x * bv.y; acc[0][2] += av.x * bv.z; acc[0][3] += av.x * bv.w;
            acc[1][0] += av.y * bv.x; acc[1][1] += av.y * bv.y; acc[1][2] += av.y * bv.z; acc[1][3] += av.y * bv.w;
            acc[2][0] += av.z * bv.x; acc[2][1] += av.z * bv.y; acc[2][2] += av.z * bv.z; acc[2][3] += av.z * bv.w;
            acc[3][0] += av.w * bv.x; acc[3][1] += av.w * bv.y; acc[3][2] += av.w * bv.z; acc[3][3] += av.w * bv.w;
        }
        __syncthreads();
    }

#pragma unroll
    for (int i = 0; i < 4; i++) {
        const int row = m0 + ty * 4 + i;
        float o0, o1, o2, o3;
        {
            const int c = n0 + tx * 4;
            o0 = acc[i][0]; o1 = acc[i][1]; o2 = acc[i][2]; o3 = acc[i][3];
            if (bias) { o0 += bias[c]; o1 += bias[c + 1]; o2 += bias[c + 2]; o3 += bias[c + 3]; }
            if (RELU) { o0 = fmaxf(o0, 0.f); o1 = fmaxf(o1, 0.f); o2 = fmaxf(o2, 0.f); o3 = fmaxf(o3, 0.f); }
        }
        *(float4*)&C[(long long)row * ldc + n0 + tx * 4] = make_float4(o0, o1, o2, o3);
    }
}

// ---------------------------------------------------------------------------
// Embedding gather + pad flags (pad row of emb is zero; tokens never hit it
// for these inputs, but implement faithfully).
// ---------------------------------------------------------------------------
__global__ void embed_kernel(const int* __restrict__ tok, const float* __restrict__ emb,
                             float* __restrict__ x, int* __restrict__ pad, int padidx)
{
    const int n = blockIdx.x;
    const int t = tok[n];
    if (threadIdx.x == 0) pad[n] = (t == padidx) ? 1 : 0;
    const float4* src = (const float4*)(emb + (size_t)t * kD);
    float4* dst = (float4*)(x + (size_t)n * kD);
    for (int i = threadIdx.x; i < kD / 4; i += blockDim.x) dst[i] = src[i];
}

// ---------------------------------------------------------------------------
// Attention softmax (in-place on raw scores): scale, key-pad mask, softmax.
// One block per (b,h,q) row; S in {256, 1024}.
// ---------------------------------------------------------------------------
__global__ void attn_softmax_kernel(float* __restrict__ scores,
                                    const int* __restrict__ pad, int S)
{
    __shared__ float sh[8];
    const long long row = blockIdx.x;
    const int b = (int)(row / ((long long)kH * S));
    float* p = scores + row * (long long)S;
    const int* pb = pad + b * S;

    float vals[4];
    const int per = S >> 8;  // S / 256
    float m = -CUDART_INF_F;
    for (int i = 0; i < per; i++) {
        const int k = threadIdx.x + (i << 8);
        const float v = pb[k] ? kNeg : p[k] * kScale;
        vals[i] = v;
        m = fmaxf(m, v);
    }
    m = block_max(m, sh);
    float s = 0.f;
    for (int i = 0; i < per; i++) {
        vals[i] = __expf(vals[i] - m);
        s += vals[i];
    }
    s = block_sum(s, sh);
    const float inv = 1.f / s;
    for (int i = 0; i < per; i++)
        p[threadIdx.x + (i << 8)] = vals[i] * inv;
}

// ---------------------------------------------------------------------------
// x = LayerNorm(x + y) * gamma + beta, one block per token row (D=1024).
// ---------------------------------------------------------------------------
__global__ void add_ln_kernel(float* __restrict__ x, const float* __restrict__ y,
                              const float* __restrict__ gamma, const float* __restrict__ beta)
{
    __shared__ float sh[8];
    const long long row = blockIdx.x;
    float* xp = x + row * kD;
    const float* yp = y + row * kD;

    float v[4];
    float s = 0.f;
#pragma unroll
    for (int i = 0; i < 4; i++) {
        const int idx = threadIdx.x + (i << 8);
        v[i] = xp[idx] + yp[idx];
        s += v[i];
    }
    s = block_sum(s, sh);
    const float mean = s * (1.f / kD);
    float sq = 0.f;
#pragma unroll
    for (int i = 0; i < 4; i++) {
        const float d = v[i] - mean;
        sq += d * d;
    }
    sq = block_sum(sq, sh);
    const float r = rsqrtf(sq * (1.f / kD) + kLnEps);
#pragma unroll
    for (int i = 0; i < 4; i++) {
        const int idx = threadIdx.x + (i << 8);
        xp[idx] = (v[i] - mean) * r * gamma[idx] + beta[idx];
    }
}

// ---------------------------------------------------------------------------
// Row squared-L2 norms.
// ---------------------------------------------------------------------------
__global__ void rownorm_kernel(const float* __restrict__ x, float* __restrict__ out)
{
    __shared__ float sh[8];
    const long long row = blockIdx.x;
    const float* xp = x + row * kD;
    float s = 0.f;
#pragma unroll
    for (int i = 0; i < 4; i++) {
        const float v = xp[threadIdx.x + (i << 8)];
        s += v * v;
    }
    s = block_sum(s, sh);
    if (threadIdx.x == 0) out[row] = s;
}

// ---------------------------------------------------------------------------
// dist = -TEMP*(|u|^2 + |t|^2 - 2 u.t), mask, log_softmax over t (in-place
// on the cross-product buffer). One block per (b,u) row; T = 256 = blockDim.
// ---------------------------------------------------------------------------
__global__ void dist_logsoftmax_kernel(float* __restrict__ out,
                                       const float* __restrict__ un,
                                       const float* __restrict__ tn,
                                       const int* __restrict__ pad_u,
                                       const int* __restrict__ pad_t)
{
    __shared__ float sh[8];
    const int row = blockIdx.x;   // b*kU + u
    const int b = row / kU;
    float* p = out + (long long)row * kT;
    const int t = threadIdx.x;

    const bool masked = (pad_u[row] != 0) || (pad_t[b * kT + t] != 0);
    const float v = masked ? kNeg
                           : -kTemp * (un[row] + tn[b * kT + t] - 2.f * p[t]);
    const float m = block_max(v, sh);
    const float e = __expf(v - m);
    const float s = block_sum(e, sh);
    p[t] = v - m - logf(s);
}

// ---------------------------------------------------------------------------
// Host orchestration
// ---------------------------------------------------------------------------
namespace {

struct EncParams {
    const float *emb, *ipw, *ipb, *ow, *ob, *l1s, *l1b,
                *f1w, *f1b, *f2w, *f2b, *l2s, *l2b;
};

void run_encoder(const int* tokens, int Slen, int padidx, const EncParams& P,
                 float* x, int* pad, float* qkv, float* scores, float* att, float* ffb)
{
    const int Ntok = kB * Slen;
    embed_kernel<<<Ntok, 256>>>(tokens, P.emb, x, pad, padidx);

    for (int l = 0; l < kL; l++) {
        const float* ipw = P.ipw + (size_t)l * 3 * kD * kD;
        const float* ipb = P.ipb + (size_t)l * 3 * kD;
        const float* ow  = P.ow  + (size_t)l * kD * kD;
        const float* ob  = P.ob  + (size_t)l * kD;
        const float* l1s = P.l1s + (size_t)l * kD;
        const float* l1b = P.l1b + (size_t)l * kD;
        const float* f1w = P.f1w + (size_t)l * kFF * kD;
        const float* f1b = P.f1b + (size_t)l * kFF;
        const float* f2w = P.f2w + (size_t)l * kD * kFF;
        const float* f2b = P.f2b + (size_t)l * kD;
        const float* l2s = P.l2s + (size_t)l * kD;
        const float* l2b = P.l2b + (size_t)l * kD;

        // qkv = x @ ipw^T + ipb   [Ntok, 3D]
        gemm64_kernel<true, false><<<dim3(3 * kD / 64, Ntok / 64, 1), 256>>>(
            x, ipw, ipb, qkv, Ntok, 3 * kD, kD, kD, kD, 3 * kD,
            1, 0, 0, 0, 0, 0, 0);

        // scores[b,h] = Q[b,h] @ K[b,h]^T   (raw, scale applied in softmax)
        gemm64_kernel<true, false><<<dim3(Slen / 64, Slen / 64, kB * kH), 256>>>(
            qkv, qkv + kD, nullptr, scores, Slen, Slen, kDH,
            3 * kD, 3 * kD, Slen,
            kH,
            (long long)Slen * 3 * kD, (long long)kDH,
            (long long)Slen * 3 * kD, (long long)kDH,
            (long long)kH * Slen * Slen, (long long)Slen * Slen);

        attn_softmax_kernel<<<kB * kH * Slen, 256>>>(scores, pad, Slen);

        // att[b,q,h*DH+d] = attn[b,h] @ V[b,h]
        gemm64_kernel<false, false><<<dim3(kDH / 64, Slen / 64, kB * kH), 256>>>(
            scores, qkv + 2 * kD, nullptr, att, Slen, kDH, Slen,
            Slen, 3 * kD, kD,
            kH,
            (long long)kH * Slen * Slen, (long long)Slen * Slen,
            (long long)Slen * 3 * kD, (long long)kDH,
            (long long)Slen * kD, (long long)kDH);

        // o = att @ ow^T + ob  -> ffb
        gemm64_kernel<true, false><<<dim3(kD / 64, Ntok / 64, 1), 256>>>(
            att, ow, ob, ffb, Ntok, kD, kD, kD, kD, kD,
            1, 0, 0, 0, 0, 0, 0);

        // x = LN(x + o)
        add_ln_kernel<<<Ntok, 256>>>(x, ffb, l1s, l1b);

        // h = relu(x @ f1w^T + f1b) -> ffb
        gemm64_kernel<true, true><<<dim3(kFF / 64, Ntok / 64, 1), 256>>>(
            x, f1w, f1b, ffb, Ntok, kFF, kD, kD, kD, kFF,
            1, 0, 0, 0, 0, 0, 0);

        // y = h @ f2w^T + f2b -> att (reused)
        gemm64_kernel<true, false><<<dim3(kD / 64, Ntok / 64, 1), 256>>>(
            ffb, f2w, f2b, att, Ntok, kD, kFF, kFF, kFF, kD,
            1, 0, 0, 0, 0, 0, 0);

        // x = LN(x + y)
        add_ln_kernel<<<Ntok, 256>>>(x, att, l2s, l2b);
    }
}

}  // namespace

extern "C" void kernel_launch(void* const* d_in, const int* in_sizes, int n_in,
                              void* d_out, int out_size)
{
    (void)in_sizes; (void)n_in; (void)out_size;
    const int* text_tokens = (const int*)d_in[0];
    const int* unit_tokens = (const int*)d_in[1];
    auto f = [&](int i) { return (const float*)d_in[i]; };
    const EncParams tP{f(2), f(3), f(4), f(5), f(6), f(7), f(8),
                       f(9), f(10), f(11), f(12), f(13), f(14)};
    const EncParams uP{f(15), f(16), f(17), f(18), f(19), f(20), f(21),
                       f(22), f(23), f(24), f(25), f(26), f(27)};
    float* out = (float*)d_out;

    float *x_u, *x_t, *qkv, *scores, *att, *ffb, *un, *tn;
    int *pad_u, *pad_t;
    cudaGetSymbolAddress((void**)&x_u, g_x_u);
    cudaGetSymbolAddress((void**)&x_t, g_x_t);
    cudaGetSymbolAddress((void**)&qkv, g_qkv);
    cudaGetSymbolAddress((void**)&scores, g_scores);
    cudaGetSymbolAddress((void**)&att, g_att);
    cudaGetSymbolAddress((void**)&ffb, g_ffb);
    cudaGetSymbolAddress((void**)&un, g_un);
    cudaGetSymbolAddress((void**)&tn, g_tn);
    cudaGetSymbolAddress((void**)&pad_u, g_pad_u);
    cudaGetSymbolAddress((void**)&pad_t, g_pad_t);

    // Two encoders (serial on the capture stream; buffers are reused).
    run_encoder(text_tokens, kT, kTextV - 1, tP, x_t, pad_t, qkv, scores, att, ffb);
    run_encoder(unit_tokens, kU, kUnitV - 1, uP, x_u, pad_u, qkv, scores, att, ffb);

    // Squared norms.
    rownorm_kernel<<<kB * kU, 256>>>(x_u, un);
    rownorm_kernel<<<kB * kT, 256>>>(x_t, tn);

    // cross[b,u,t] = uf . tf  (into out), batched over b.
    gemm64_kernel<true, false><<<dim3(kT / 64, kU / 64, kB), 256>>>(
        x_u, x_t, nullptr, out, kU, kT, kD, kD, kD, kT,
        1, (long long)kU * kD, 0, (long long)kT * kD, 0,
        (long long)kU * kT, 0);

    // dist + mask + log_softmax (in place on out).
    dist_logsoftmax_kernel<<<kB * kU, 256>>>(out, un, tn, pad_u, pad_t);
}

// round 3
// speedup vs baseline: 3.2572x; 3.2572x over previous
#include <cuda_runtime.h>
#include <math_constants.h>
#include <math.h>
#include <cstdint>

// ---------------------------------------------------------------------------
// Problem constants
// ---------------------------------------------------------------------------
namespace {
constexpr int kD  = 1024;
constexpr int kH  = 8;
constexpr int kFF = 2048;
constexpr int kL  = 3;
constexpr int kB  = 8;
constexpr int kT  = 256;
constexpr int kU  = 1024;
constexpr int kTextV = 128257;
constexpr int kUnitV = 10001;
constexpr float kLnEps = 1e-5f;
constexpr float kTemp  = 0.0005f;
constexpr float kNeg   = -1e9f;
constexpr float kScale = 0.08838834764831845f;  // 1/sqrt(128)
}

// ---------------------------------------------------------------------------
// Scratch (device globals; no allocations allowed)
// ---------------------------------------------------------------------------
__device__ float g_x_u[kB * kU * kD];                 // 32 MB
__device__ float g_x_t[kB * kT * kD];                 // 8 MB
__device__ float g_qkv[kB * kU * 3 * kD];             // 96 MB
__device__ float g_scores[(size_t)kB * kH * kU * kU]; // 256 MB
__device__ float g_att[kB * kU * kD];                 // 32 MB
__device__ float g_ffb[kB * kU * kFF];                // 64 MB
__device__ float g_vt[kB * kH * 128 * kU];            // 32 MB (V transposed)
__device__ float g_un[kB * kU];
__device__ float g_tn[kB * kT];
__device__ int   g_pad_u[kB * kU];
__device__ int   g_pad_t[kB * kT];

// ---------------------------------------------------------------------------
// PTX helpers
// ---------------------------------------------------------------------------
__device__ __forceinline__ uint32_t smem_u32(const void* p) {
    return (uint32_t)__cvta_generic_to_shared(p);
}
__device__ __forceinline__ void cp_async16(uint32_t dst, const float* src) {
    asm volatile("cp.async.cg.shared.global [%0], [%1], 16;"
                 :: "r"(dst), "l"(__cvta_generic_to_global(src)));
}
#define CP_COMMIT() asm volatile("cp.async.commit_group;" ::: "memory")
#define CP_WAIT(n)  asm volatile("cp.async.wait_group %0;" :: "n"(n) : "memory")

__device__ __forceinline__ void mma_tf32(float* d, const uint32_t* a, const uint32_t* b) {
    asm volatile(
        "mma.sync.aligned.m16n8k8.row.col.f32.tf32.tf32.f32 "
        "{%0,%1,%2,%3}, {%4,%5,%6,%7}, {%8,%9}, {%0,%1,%2,%3};"
        : "+f"(d[0]), "+f"(d[1]), "+f"(d[2]), "+f"(d[3])
        : "r"(a[0]), "r"(a[1]), "r"(a[2]), "r"(a[3]), "r"(b[0]), "r"(b[1]));
}

// ---------------------------------------------------------------------------
// Tensor-core tf32 GEMM:  C = act(A @ B^T + bias)
//   A: [M, K] row-major, lda elems.  B: [N, K] row-major, ldb elems.
//   CTA tile 128(M) x BN(N) x 32(K); 8 warps (2x4), warp tile 64 x BN/4.
//   3-stage cp.async pipeline. fp32 in memory, tf32 in the MMA (HW truncation).
//   Batched via blockIdx.z = zo*innerB + zi with per-operand strides.
// REQUIRES: M % 128 == 0, N % BN == 0, K % 32 == 0 (true at all call sites).
// ---------------------------------------------------------------------------
template <int BN, bool RELU>
__global__ void __launch_bounds__(256, 1)
tc_gemm(const float* __restrict__ A, const float* __restrict__ B,
        const float* __restrict__ bias, float* __restrict__ C,
        int K, int lda, int ldb, int ldc, int innerB,
        long long sAo, long long sAi, long long sBo, long long sBi,
        long long sCo, long long sCi)
{
    constexpr int BM  = 128;
    constexpr int STR = 36;                 // smem row stride (floats), pad 4
    constexpr int NWT = BN / 4;             // warp tile N
    constexpr int NJ  = NWT / 8;            // n-frags per warp
    constexpr int A_FLOATS = BM * STR;
    constexpr int B_FLOATS = BN * STR;
    constexpr int STAGE = A_FLOATS + B_FLOATS;

    extern __shared__ float sm[];

    const int z  = blockIdx.z;
    const int zo = z / innerB;
    const int zi = z - zo * innerB;
    A += zo * sAo + zi * sAi;
    B += zo * sBo + zi * sBi;
    C += zo * sCo + zi * sCi;

    const int m0 = blockIdx.y * BM;
    const int n0 = blockIdx.x * BN;
    const int tid = threadIdx.x;
    const int wid = tid >> 5;
    const int lane = tid & 31;
    const int mw = wid >> 2;                // 0..1
    const int nw = wid & 3;                 // 0..3
    const int gr = lane >> 2;               // 0..7
    const int q  = lane & 3;                // 0..3

    const float* Ag = A + (long long)m0 * lda;
    const float* Bg = B + (long long)n0 * ldb;

    auto load_stage = [&](int it) {
        float* s = sm + (it % 3) * STAGE;
        const int kof = it * 32;
#pragma unroll
        for (int i = 0; i < 4; i++) {              // A: 128 rows x 8 chunks
            const int c = tid + i * 256;
            const int r = c >> 3, kc = c & 7;
            cp_async16(smem_u32(s + r * STR + kc * 4),
                       Ag + (long long)r * lda + kof + kc * 4);
        }
#pragma unroll
        for (int i = 0; i < BN / 32; i++) {        // B: BN rows x 8 chunks
            const int c = tid + i * 256;
            const int r = c >> 3, kc = c & 7;
            cp_async16(smem_u32(s + A_FLOATS + r * STR + kc * 4),
                       Bg + (long long)r * ldb + kof + kc * 4);
        }
        CP_COMMIT();
    };

    const int KT = K >> 5;
    load_stage(0);
    if (KT > 1) load_stage(1);

    float acc[4][NJ][4];
#pragma unroll
    for (int i = 0; i < 4; i++)
#pragma unroll
        for (int j = 0; j < NJ; j++)
#pragma unroll
            for (int r = 0; r < 4; r++) acc[i][j][r] = 0.f;

    for (int it = 0; it < KT; it++) {
        if (it + 1 < KT) { CP_WAIT(1); } else { CP_WAIT(0); }
        __syncthreads();
        if (it + 2 < KT) load_stage(it + 2);

        const float* sA = sm + (it % 3) * STAGE;
        const float* sB = sA + A_FLOATS;

#pragma unroll
        for (int ks = 0; ks < 4; ks++) {
            const int k0 = ks * 8;
            uint32_t a[4][4];
#pragma unroll
            for (int i = 0; i < 4; i++) {
                const float* p = sA + (mw * 64 + i * 16 + gr) * STR + k0 + q;
                a[i][0] = __float_as_uint(p[0]);
                a[i][1] = __float_as_uint(p[8 * STR]);
                a[i][2] = __float_as_uint(p[4]);
                a[i][3] = __float_as_uint(p[8 * STR + 4]);
            }
            uint32_t b[NJ][2];
#pragma unroll
            for (int j = 0; j < NJ; j++) {
                const float* p = sB + (nw * NWT + j * 8 + gr) * STR + k0 + q;
                b[j][0] = __float_as_uint(p[0]);
                b[j][1] = __float_as_uint(p[4]);
            }
#pragma unroll
            for (int i = 0; i < 4; i++)
#pragma unroll
                for (int j = 0; j < NJ; j++)
                    mma_tf32(acc[i][j], a[i], b[j]);
        }
    }

    // Epilogue: d0=C[gr][q*2], d1=C[gr][q*2+1], d2=C[gr+8][q*2], d3=C[gr+8][q*2+1]
#pragma unroll
    for (int i = 0; i < 4; i++) {
        const int r0 = m0 + mw * 64 + i * 16 + gr;
#pragma unroll
        for (int j = 0; j < NJ; j++) {
            const int cc = n0 + nw * NWT + j * 8 + q * 2;
            float2 v0 = make_float2(acc[i][j][0], acc[i][j][1]);
            float2 v1 = make_float2(acc[i][j][2], acc[i][j][3]);
            if (bias) {
                const float2 bb = *(const float2*)(bias + cc);
                v0.x += bb.x; v0.y += bb.y;
                v1.x += bb.x; v1.y += bb.y;
            }
            if (RELU) {
                v0.x = fmaxf(v0.x, 0.f); v0.y = fmaxf(v0.y, 0.f);
                v1.x = fmaxf(v1.x, 0.f); v1.y = fmaxf(v1.y, 0.f);
            }
            *(float2*)(C + (long long)r0 * ldc + cc) = v0;
            *(float2*)(C + (long long)(r0 + 8) * ldc + cc) = v1;
        }
    }
}

// ---------------------------------------------------------------------------
// V transpose: vt[b,h,d,s] = qkv[b,s, 2D + h*128 + d]
// ---------------------------------------------------------------------------
__global__ void transpose_v(const float* __restrict__ qkv, float* __restrict__ vt, int S)
{
    __shared__ float t[32][33];
    const int bh = blockIdx.z;
    const int b = bh >> 3, h = bh & 7;
    const int s0 = blockIdx.x * 32, d0 = blockIdx.y * 32;
    const float* src = qkv + (long long)b * S * 3072 + 2048 + h * 128;
    for (int i = threadIdx.y; i < 32; i += 8)
        t[i][threadIdx.x] = src[(long long)(s0 + i) * 3072 + d0 + threadIdx.x];
    __syncthreads();
    float* dst = vt + ((long long)bh * 128 + d0) * S + s0;
    for (int i = threadIdx.y; i < 32; i += 8)
        dst[(long long)i * S + threadIdx.x] = t[threadIdx.x][i];
}

// ---------------------------------------------------------------------------
// Reduction helpers (blockDim.x == 256)
// ---------------------------------------------------------------------------
__device__ __forceinline__ float warp_sum(float v) {
#pragma unroll
    for (int o = 16; o > 0; o >>= 1) v += __shfl_xor_sync(0xffffffffu, v, o);
    return v;
}
__device__ __forceinline__ float warp_max(float v) {
#pragma unroll
    for (int o = 16; o > 0; o >>= 1) v = fmaxf(v, __shfl_xor_sync(0xffffffffu, v, o));
    return v;
}
__device__ __forceinline__ float block_sum(float v, float* sh) {
    v = warp_sum(v);
    if ((threadIdx.x & 31) == 0) sh[threadIdx.x >> 5] = v;
    __syncthreads();
    float r = 0.f;
#pragma unroll
    for (int i = 0; i < 8; i++) r += sh[i];
    __syncthreads();
    return r;
}
__device__ __forceinline__ float block_max(float v, float* sh) {
    v = warp_max(v);
    if ((threadIdx.x & 31) == 0) sh[threadIdx.x >> 5] = v;
    __syncthreads();
    float r = -CUDART_INF_F;
#pragma unroll
    for (int i = 0; i < 8; i++) r = fmaxf(r, sh[i]);
    __syncthreads();
    return r;
}

// ---------------------------------------------------------------------------
// Elementwise / reduction kernels
// ---------------------------------------------------------------------------
__global__ void embed_kernel(const int* __restrict__ tok, const float* __restrict__ emb,
                             float* __restrict__ x, int* __restrict__ pad, int padidx)
{
    const int n = blockIdx.x;
    const int t = tok[n];
    if (threadIdx.x == 0) pad[n] = (t == padidx) ? 1 : 0;
    const float4* src = (const float4*)(emb + (size_t)t * kD);
    float4* dst = (float4*)(x + (size_t)n * kD);
    for (int i = threadIdx.x; i < kD / 4; i += blockDim.x) dst[i] = src[i];
}

__global__ void attn_softmax_kernel(float* __restrict__ scores,
                                    const int* __restrict__ pad, int S)
{
    __shared__ float sh[8];
    const long long row = blockIdx.x;
    const int b = (int)(row / ((long long)kH * S));
    float* p = scores + row * (long long)S;
    const int* pb = pad + b * S;

    float vals[4];
    const int per = S >> 8;
    float m = -CUDART_INF_F;
    for (int i = 0; i < per; i++) {
        const int k = threadIdx.x + (i << 8);
        const float v = pb[k] ? kNeg : p[k] * kScale;
        vals[i] = v;
        m = fmaxf(m, v);
    }
    m = block_max(m, sh);
    float s = 0.f;
    for (int i = 0; i < per; i++) { vals[i] = __expf(vals[i] - m); s += vals[i]; }
    s = block_sum(s, sh);
    const float inv = 1.f / s;
    for (int i = 0; i < per; i++) p[threadIdx.x + (i << 8)] = vals[i] * inv;
}

__global__ void add_ln_kernel(float* __restrict__ x, const float* __restrict__ y,
                              const float* __restrict__ gamma, const float* __restrict__ beta)
{
    __shared__ float sh[8];
    const long long row = blockIdx.x;
    float* xp = x + row * kD;
    const float* yp = y + row * kD;

    float v[4];
    float s = 0.f;
#pragma unroll
    for (int i = 0; i < 4; i++) {
        const int idx = threadIdx.x + (i << 8);
        v[i] = xp[idx] + yp[idx];
        s += v[i];
    }
    s = block_sum(s, sh);
    const float mean = s * (1.f / kD);
    float sq = 0.f;
#pragma unroll
    for (int i = 0; i < 4; i++) { const float d = v[i] - mean; sq += d * d; }
    sq = block_sum(sq, sh);
    const float r = rsqrtf(sq * (1.f / kD) + kLnEps);
#pragma unroll
    for (int i = 0; i < 4; i++) {
        const int idx = threadIdx.x + (i << 8);
        xp[idx] = (v[i] - mean) * r * gamma[idx] + beta[idx];
    }
}

__global__ void rownorm_kernel(const float* __restrict__ x, float* __restrict__ out)
{
    __shared__ float sh[8];
    const long long row = blockIdx.x;
    const float* xp = x + row * kD;
    float s = 0.f;
#pragma unroll
    for (int i = 0; i < 4; i++) {
        const float v = xp[threadIdx.x + (i << 8)];
        s += v * v;
    }
    s = block_sum(s, sh);
    if (threadIdx.x == 0) out[row] = s;
}

__global__ void dist_logsoftmax_kernel(float* __restrict__ out,
                                       const float* __restrict__ un,
                                       const float* __restrict__ tn,
                                       const int* __restrict__ pad_u,
                                       const int* __restrict__ pad_t)
{
    __shared__ float sh[8];
    const int row = blockIdx.x;
    const int b = row / kU;
    float* p = out + (long long)row * kT;
    const int t = threadIdx.x;

    const bool masked = (pad_u[row] != 0) || (pad_t[b * kT + t] != 0);
    const float v = masked ? kNeg
                           : -kTemp * (un[row] + tn[b * kT + t] - 2.f * p[t]);
    const float m = block_max(v, sh);
    const float e = __expf(v - m);
    const float s = block_sum(e, sh);
    p[t] = v - m - logf(s);
}

// ---------------------------------------------------------------------------
// Host orchestration
// ---------------------------------------------------------------------------
namespace {

constexpr size_t kSmem256 = 3 * (128 + 256) * 36 * sizeof(float);  // 165888
constexpr size_t kSmem128 = 3 * (128 + 128) * 36 * sizeof(float);  // 110592

struct EncParams {
    const float *emb, *ipw, *ipb, *ow, *ob, *l1s, *l1b,
                *f1w, *f1b, *f2w, *f2b, *l2s, *l2b;
};

void run_encoder(const int* tokens, int Slen, int padidx, const EncParams& P,
                 float* x, int* pad, float* qkv, float* scores, float* att,
                 float* ffb, float* vt)
{
    const int Ntok = kB * Slen;
    embed_kernel<<<Ntok, 256>>>(tokens, P.emb, x, pad, padidx);

    for (int l = 0; l < kL; l++) {
        const float* ipw = P.ipw + (size_t)l * 3 * kD * kD;
        const float* ipb = P.ipb + (size_t)l * 3 * kD;
        const float* ow  = P.ow  + (size_t)l * kD * kD;
        const float* ob  = P.ob  + (size_t)l * kD;
        const float* l1s = P.l1s + (size_t)l * kD;
        const float* l1b = P.l1b + (size_t)l * kD;
        const float* f1w = P.f1w + (size_t)l * kFF * kD;
        const float* f1b = P.f1b + (size_t)l * kFF;
        const float* f2w = P.f2w + (size_t)l * kD * kFF;
        const float* f2b = P.f2b + (size_t)l * kD;
        const float* l2s = P.l2s + (size_t)l * kD;
        const float* l2b = P.l2b + (size_t)l * kD;

        // qkv = x @ ipw^T + ipb   [Ntok, 3D]
        tc_gemm<256, false><<<dim3(3 * kD / 256, Ntok / 128, 1), 256, kSmem256>>>(
            x, ipw, ipb, qkv, kD, kD, kD, 3 * kD, 1, 0, 0, 0, 0, 0, 0);

        // vt[b,h,d,s] = V
        transpose_v<<<dim3(Slen / 32, 4, kB * kH), dim3(32, 8)>>>(qkv, vt, Slen);

        // scores[b,h] = Q[b,h] @ K[b,h]^T (raw; scale applied in softmax)
        tc_gemm<256, false><<<dim3(Slen / 256, Slen / 128, kB * kH), 256, kSmem256>>>(
            qkv, qkv + kD, nullptr, scores, 128, 3 * kD, 3 * kD, Slen,
            kH,
            (long long)Slen * 3 * kD, 128LL,
            (long long)Slen * 3 * kD, 128LL,
            (long long)kH * Slen * Slen, (long long)Slen * Slen);

        attn_softmax_kernel<<<kB * kH * Slen, 256>>>(scores, pad, Slen);

        // att[b,q,h*128+d] = attn[b,h] @ vt[b,h]^T
        tc_gemm<128, false><<<dim3(1, Slen / 128, kB * kH), 256, kSmem128>>>(
            scores, vt, nullptr, att, Slen, Slen, Slen, kD,
            kH,
            (long long)kH * Slen * Slen, (long long)Slen * Slen,
            (long long)kH * 128 * Slen, (long long)128 * Slen,
            (long long)Slen * kD, 128LL);

        // o = att @ ow^T + ob -> ffb
        tc_gemm<256, false><<<dim3(kD / 256, Ntok / 128, 1), 256, kSmem256>>>(
            att, ow, ob, ffb, kD, kD, kD, kD, 1, 0, 0, 0, 0, 0, 0);

        add_ln_kernel<<<Ntok, 256>>>(x, ffb, l1s, l1b);

        // h = relu(x @ f1w^T + f1b) -> ffb
        tc_gemm<256, true><<<dim3(kFF / 256, Ntok / 128, 1), 256, kSmem256>>>(
            x, f1w, f1b, ffb, kD, kD, kD, kFF, 1, 0, 0, 0, 0, 0, 0);

        // y = h @ f2w^T + f2b -> att (reused)
        tc_gemm<256, false><<<dim3(kD / 256, Ntok / 128, 1), 256, kSmem256>>>(
            ffb, f2w, f2b, att, kFF, kFF, kFF, kD, 1, 0, 0, 0, 0, 0, 0);

        add_ln_kernel<<<Ntok, 256>>>(x, att, l2s, l2b);
    }
}

}  // namespace

extern "C" void kernel_launch(void* const* d_in, const int* in_sizes, int n_in,
                              void* d_out, int out_size)
{
    (void)in_sizes; (void)n_in; (void)out_size;
    const int* text_tokens = (const int*)d_in[0];
    const int* unit_tokens = (const int*)d_in[1];
    auto f = [&](int i) { return (const float*)d_in[i]; };
    const EncParams tP{f(2), f(3), f(4), f(5), f(6), f(7), f(8),
                       f(9), f(10), f(11), f(12), f(13), f(14)};
    const EncParams uP{f(15), f(16), f(17), f(18), f(19), f(20), f(21),
                       f(22), f(23), f(24), f(25), f(26), f(27)};
    float* out = (float*)d_out;

    cudaFuncSetAttribute(tc_gemm<256, false>,
                         cudaFuncAttributeMaxDynamicSharedMemorySize, (int)kSmem256);
    cudaFuncSetAttribute(tc_gemm<256, true>,
                         cudaFuncAttributeMaxDynamicSharedMemorySize, (int)kSmem256);
    cudaFuncSetAttribute(tc_gemm<128, false>,
                         cudaFuncAttributeMaxDynamicSharedMemorySize, (int)kSmem128);

    float *x_u, *x_t, *qkv, *scores, *att, *ffb, *vt, *un, *tn;
    int *pad_u, *pad_t;
    cudaGetSymbolAddress((void**)&x_u, g_x_u);
    cudaGetSymbolAddress((void**)&x_t, g_x_t);
    cudaGetSymbolAddress((void**)&qkv, g_qkv);
    cudaGetSymbolAddress((void**)&scores, g_scores);
    cudaGetSymbolAddress((void**)&att, g_att);
    cudaGetSymbolAddress((void**)&ffb, g_ffb);
    cudaGetSymbolAddress((void**)&vt, g_vt);
    cudaGetSymbolAddress((void**)&un, g_un);
    cudaGetSymbolAddress((void**)&tn, g_tn);
    cudaGetSymbolAddress((void**)&pad_u, g_pad_u);
    cudaGetSymbolAddress((void**)&pad_t, g_pad_t);

    run_encoder(text_tokens, kT, kTextV - 1, tP, x_t, pad_t, qkv, scores, att, ffb, vt);
    run_encoder(unit_tokens, kU, kUnitV - 1, uP, x_u, pad_u, qkv, scores, att, ffb, vt);

    rownorm_kernel<<<kB * kU, 256>>>(x_u, un);
    rownorm_kernel<<<kB * kT, 256>>>(x_t, tn);

    // cross[b,u,t] = uf . tf (into out), batched over b
    tc_gemm<256, false><<<dim3(kT / 256, kU / 128, kB), 256, kSmem256>>>(
        x_u, x_t, nullptr, out, kD, kD, kD, kT,
        1, (long long)kU * kD, 0, (long long)kT * kD, 0,
        (long long)kU * kT, 0);

    dist_logsoftmax_kernel<<<kB * kU, 256>>>(out, un, tn, pad_u, pad_t);
}

// round 4
// speedup vs baseline: 6.0961x; 1.8716x over previous
#include <cuda_runtime.h>
#include <cuda_bf16.h>
#include <math_constants.h>
#include <math.h>
#include <cstdint>

// ---------------------------------------------------------------------------
// Problem constants
// ---------------------------------------------------------------------------
namespace {
constexpr int kD  = 1024;
constexpr int kH  = 8;
constexpr int kFF = 2048;
constexpr int kL  = 3;
constexpr int kB  = 8;
constexpr int kT  = 256;
constexpr int kU  = 1024;
constexpr int kTextV = 128257;
constexpr int kUnitV = 10001;
constexpr float kLnEps = 1e-5f;
constexpr float kTemp  = 0.0005f;
constexpr float kNeg   = -1e9f;
constexpr float kScale = 0.08838834764831845f;  // 1/sqrt(128)
// bf16 weight scratch layout (per encoder): [ipw | ow | f1w | f2w]
constexpr long long kWipw = (long long)kL * 3 * kD * kD;  // 9437184
constexpr long long kWow  = (long long)kL * kD * kD;      // 3145728
constexpr long long kWf1  = (long long)kL * kFF * kD;     // 6291456
constexpr long long kWf2  = (long long)kL * kD * kFF;     // 6291456
constexpr long long kWEnc = kWipw + kWow + kWf1 + kWf2;   // 25165824
}

// ---------------------------------------------------------------------------
// Scratch (device globals; no allocations allowed)
// ---------------------------------------------------------------------------
__device__ __nv_bfloat16 g_x_u[kB * kU * kD];
__device__ __nv_bfloat16 g_x_t[kB * kT * kD];
__device__ __nv_bfloat16 g_qkv[kB * kU * 3 * kD];
__device__ float         g_scores[(size_t)kB * kH * kU * kU];  // fp32 scores
__device__ __nv_bfloat16 g_probs[(size_t)kB * kH * kU * kU];   // bf16 probs
__device__ __nv_bfloat16 g_att[kB * kU * kD];
__device__ __nv_bfloat16 g_tmp[kB * kU * kD];
__device__ __nv_bfloat16 g_ffb[kB * kU * kFF];
__device__ __nv_bfloat16 g_vt[kB * kH * 128 * kU];
__device__ __nv_bfloat16 g_wbf[2 * kWEnc];
__device__ float g_un[kB * kU];
__device__ float g_tn[kB * kT];
__device__ int   g_pad_u[kB * kU];
__device__ int   g_pad_t[kB * kT];

// ---------------------------------------------------------------------------
// PTX helpers
// ---------------------------------------------------------------------------
__device__ __forceinline__ uint32_t smem_u32(const void* p) {
    return (uint32_t)__cvta_generic_to_shared(p);
}
__device__ __forceinline__ void cp_async16(uint32_t dst, const void* src) {
    asm volatile("cp.async.cg.shared.global [%0], [%1], 16;"
                 :: "r"(dst), "l"(__cvta_generic_to_global(src)));
}
#define CP_COMMIT() asm volatile("cp.async.commit_group;" ::: "memory")
#define CP_WAIT(n)  asm volatile("cp.async.wait_group %0;" :: "n"(n) : "memory")

__device__ __forceinline__ void ldmx4(uint32_t* r, uint32_t a) {
    asm volatile("ldmatrix.sync.aligned.m8n8.x4.shared.b16 {%0,%1,%2,%3}, [%4];"
                 : "=r"(r[0]), "=r"(r[1]), "=r"(r[2]), "=r"(r[3]) : "r"(a));
}
__device__ __forceinline__ void mma_bf16(float* d, const uint32_t* a, const uint32_t* b) {
    asm volatile(
        "mma.sync.aligned.m16n8k16.row.col.f32.bf16.bf16.f32 "
        "{%0,%1,%2,%3}, {%4,%5,%6,%7}, {%8,%9}, {%0,%1,%2,%3};"
        : "+f"(d[0]), "+f"(d[1]), "+f"(d[2]), "+f"(d[3])
        : "r"(a[0]), "r"(a[1]), "r"(a[2]), "r"(a[3]), "r"(b[0]), "r"(b[1]));
}

template <typename OutT>
__device__ __forceinline__ void store2(OutT* p, float x, float y);
template <>
__device__ __forceinline__ void store2<float>(float* p, float x, float y) {
    *(float2*)p = make_float2(x, y);
}
template <>
__device__ __forceinline__ void store2<__nv_bfloat16>(__nv_bfloat16* p, float x, float y) {
    *(__nv_bfloat162*)p = __floats2bfloat162_rn(x, y);
}

// ---------------------------------------------------------------------------
// bf16 tensor-core GEMM:  C = act(A @ B^T + bias)
//   A: [M,K] bf16 row-major; B: [N,K] bf16 row-major; C: OutT (fp32 or bf16).
//   CTA tile 128x128x32, 8 warps (2x4), warp tile 64x32, ldmatrix fragments,
//   4-stage cp.async pipeline (80KB smem), 2 CTAs/SM.
//   smem rows: 80B stride (32 bf16 + 8 pad) -> ldmatrix chunk pos (5r+c)%8
//   conflict-free. Batched via blockIdx.z = zo*innerB + zi.
// REQUIRES: M%128==0, N%128==0, K%32==0, lda/ldb mult of 8. (all call sites)
// ---------------------------------------------------------------------------
template <typename OutT, bool RELU>
__global__ void __launch_bounds__(256, 2)
bf_gemm(const __nv_bfloat16* __restrict__ A, const __nv_bfloat16* __restrict__ B,
        const float* __restrict__ bias, OutT* __restrict__ C,
        int K, int lda, int ldb, int ldc, int innerB,
        long long sAo, long long sAi, long long sBo, long long sBi,
        long long sCo, long long sCi)
{
    constexpr int STAGE = 256 * 80;          // bytes per stage
    extern __shared__ char sm[];
    const uint32_t sbase = smem_u32(sm);

    const int z  = blockIdx.z;
    const int zo = z / innerB;
    const int zi = z - zo * innerB;
    A += zo * sAo + zi * sAi;
    B += zo * sBo + zi * sBi;
    C += zo * sCo + zi * sCi;

    const int m0 = blockIdx.y * 128;
    const int n0 = blockIdx.x * 128;
    const int tid = threadIdx.x;
    const int lane = tid & 31;
    const int wid = tid >> 5;
    const int mw = wid >> 2;      // 0..1
    const int nw = wid & 3;       // 0..3

    const __nv_bfloat16* Ag = A + (long long)m0 * lda;
    const __nv_bfloat16* Bg = B + (long long)n0 * ldb;

    auto load_stage = [&](int it) {
        const uint32_t s = sbase + (it & 3) * STAGE;
        const int kof = it * 32;
#pragma unroll
        for (int i = 0; i < 4; i++) {        // 1024 16B chunks / 256 threads
            const int c = tid + i * 256;
            const int r = c >> 2, cc = c & 3;
            const __nv_bfloat16* src =
                (r < 128) ? Ag + (long long)r * lda + kof + cc * 8
                          : Bg + (long long)(r - 128) * ldb + kof + cc * 8;
            cp_async16(s + r * 80 + cc * 16, src);
        }
        CP_COMMIT();
    };

    const int KT = K >> 5;
    load_stage(0);
    if (KT > 1) load_stage(1);
    if (KT > 2) load_stage(2);

    float acc[4][4][4] = {};

    for (int it = 0; it < KT; it++) {
        const int rem = KT - 1 - it;
        if (rem >= 2)      CP_WAIT(2);
        else if (rem == 1) CP_WAIT(1);
        else               CP_WAIT(0);
        __syncthreads();
        const uint32_t s = sbase + (it & 3) * STAGE;

#pragma unroll
        for (int ks = 0; ks < 2; ks++) {
            uint32_t a[4][4], b[2][4];
#pragma unroll
            for (int i = 0; i < 4; i++) {
                const int row = mw * 64 + i * 16 + (lane & 15);
                ldmx4(a[i], s + row * 80 + (ks * 2 + (lane >> 4)) * 16);
            }
#pragma unroll
            for (int jj = 0; jj < 2; jj++) {
                const int row = 128 + nw * 32 + jj * 16 + (lane & 7) + ((lane >> 4) << 3);
                ldmx4(b[jj], s + row * 80 + (ks * 2 + ((lane >> 3) & 1)) * 16);
            }
#pragma unroll
            for (int i = 0; i < 4; i++)
#pragma unroll
                for (int j = 0; j < 4; j++)
                    mma_bf16(acc[i][j], a[i], &b[j >> 1][(j & 1) * 2]);
        }
        if (it + 3 < KT) load_stage(it + 3);
    }

    // Epilogue: d0,d1 = (row, col..col+1); d2,d3 = (row+8, col..col+1)
    const int r4 = lane >> 2;
    const int c2 = (lane & 3) * 2;
#pragma unroll
    for (int i = 0; i < 4; i++) {
        const int row = m0 + mw * 64 + i * 16 + r4;
#pragma unroll
        for (int j = 0; j < 4; j++) {
            const int col = n0 + nw * 32 + j * 8 + c2;
            float x0 = acc[i][j][0], x1 = acc[i][j][1];
            float x2 = acc[i][j][2], x3 = acc[i][j][3];
            if (bias) {
                const float2 bb = *(const float2*)(bias + col);
                x0 += bb.x; x1 += bb.y; x2 += bb.x; x3 += bb.y;
            }
            if (RELU) {
                x0 = fmaxf(x0, 0.f); x1 = fmaxf(x1, 0.f);
                x2 = fmaxf(x2, 0.f); x3 = fmaxf(x3, 0.f);
            }
            store2(C + (long long)row * ldc + col, x0, x1);
            store2(C + (long long)(row + 8) * ldc + col, x2, x3);
        }
    }
}

// ---------------------------------------------------------------------------
// fp32 -> bf16 bulk convert (weights)
// ---------------------------------------------------------------------------
__global__ void f2bf_kernel(const float* __restrict__ in,
                            __nv_bfloat16* __restrict__ out, int n)
{
    const int i = (blockIdx.x * 256 + threadIdx.x) * 4;
    if (i >= n) return;
    const float4 v = *(const float4*)(in + i);
    *(__nv_bfloat162*)(out + i)     = __floats2bfloat162_rn(v.x, v.y);
    *(__nv_bfloat162*)(out + i + 2) = __floats2bfloat162_rn(v.z, v.w);
}

// ---------------------------------------------------------------------------
// Embedding gather (fp32 table -> bf16 activations) + pad flags
// ---------------------------------------------------------------------------
__global__ void embed_kernel(const int* __restrict__ tok, const float* __restrict__ emb,
                             __nv_bfloat16* __restrict__ x, int* __restrict__ pad, int padidx)
{
    const int n = blockIdx.x;
    const int t = tok[n];
    if (threadIdx.x == 0) pad[n] = (t == padidx) ? 1 : 0;
    const float4* src = (const float4*)(emb + (size_t)t * kD);
    __nv_bfloat162* dst = (__nv_bfloat162*)(x + (size_t)n * kD);
    for (int i = threadIdx.x; i < kD / 4; i += blockDim.x) {
        const float4 v = src[i];
        dst[i * 2]     = __floats2bfloat162_rn(v.x, v.y);
        dst[i * 2 + 1] = __floats2bfloat162_rn(v.z, v.w);
    }
}

// ---------------------------------------------------------------------------
// V transpose (bf16): vt[b,h,d,s] = qkv[b,s, 2D + h*128 + d]
// ---------------------------------------------------------------------------
__global__ void transpose_v(const __nv_bfloat16* __restrict__ qkv,
                            __nv_bfloat16* __restrict__ vt, int S)
{
    __shared__ __nv_bfloat16 t[32][34];
    const int bh = blockIdx.z;
    const int b = bh >> 3, h = bh & 7;
    const int s0 = blockIdx.x * 32, d0 = blockIdx.y * 32;
    const __nv_bfloat16* src = qkv + (long long)b * S * 3072 + 2048 + h * 128;
    for (int i = threadIdx.y; i < 32; i += 8)
        t[i][threadIdx.x] = src[(long long)(s0 + i) * 3072 + d0 + threadIdx.x];
    __syncthreads();
    __nv_bfloat16* dst = vt + ((long long)bh * 128 + d0) * S + s0;
    for (int i = threadIdx.y; i < 32; i += 8)
        dst[(long long)i * S + threadIdx.x] = t[threadIdx.x][i];
}

// ---------------------------------------------------------------------------
// Reduction helpers (blockDim.x == 256)
// ---------------------------------------------------------------------------
__device__ __forceinline__ float warp_sum(float v) {
#pragma unroll
    for (int o = 16; o > 0; o >>= 1) v += __shfl_xor_sync(0xffffffffu, v, o);
    return v;
}
__device__ __forceinline__ float warp_max(float v) {
#pragma unroll
    for (int o = 16; o > 0; o >>= 1) v = fmaxf(v, __shfl_xor_sync(0xffffffffu, v, o));
    return v;
}
__device__ __forceinline__ float block_sum(float v, float* sh) {
    v = warp_sum(v);
    if ((threadIdx.x & 31) == 0) sh[threadIdx.x >> 5] = v;
    __syncthreads();
    float r = 0.f;
#pragma unroll
    for (int i = 0; i < 8; i++) r += sh[i];
    __syncthreads();
    return r;
}
__device__ __forceinline__ float block_max(float v, float* sh) {
    v = warp_max(v);
    if ((threadIdx.x & 31) == 0) sh[threadIdx.x >> 5] = v;
    __syncthreads();
    float r = -CUDART_INF_F;
#pragma unroll
    for (int i = 0; i < 8; i++) r = fmaxf(r, sh[i]);
    __syncthreads();
    return r;
}

// ---------------------------------------------------------------------------
// Softmax: fp32 scores in -> bf16 probs out. One block per (b,h,q) row.
// ---------------------------------------------------------------------------
__global__ void attn_softmax_kernel(const float* __restrict__ scores,
                                    __nv_bfloat16* __restrict__ probs,
                                    const int* __restrict__ pad, int S)
{
    __shared__ float sh[8];
    const long long row = blockIdx.x;
    const int b = (int)(row / ((long long)kH * S));
    const float* p = scores + row * (long long)S;
    __nv_bfloat16* o = probs + row * (long long)S;
    const int* pb = pad + b * S;

    float vals[4];
    const int per = S >> 8;
    float m = -CUDART_INF_F;
    for (int i = 0; i < per; i++) {
        const int k = threadIdx.x + (i << 8);
        const float v = pb[k] ? kNeg : p[k] * kScale;
        vals[i] = v;
        m = fmaxf(m, v);
    }
    m = block_max(m, sh);
    float s = 0.f;
    for (int i = 0; i < per; i++) { vals[i] = __expf(vals[i] - m); s += vals[i]; }
    s = block_sum(s, sh);
    const float inv = 1.f / s;
    for (int i = 0; i < per; i++)
        o[threadIdx.x + (i << 8)] = __float2bfloat16_rn(vals[i] * inv);
}

// ---------------------------------------------------------------------------
// x = LayerNorm(x + y) (bf16 in/out; fp32 math; fp32 gamma/beta)
// ---------------------------------------------------------------------------
__global__ void add_ln_kernel(__nv_bfloat16* __restrict__ x,
                              const __nv_bfloat16* __restrict__ y,
                              const float* __restrict__ gamma,
                              const float* __restrict__ beta)
{
    __shared__ float sh[8];
    const long long row = blockIdx.x;
    __nv_bfloat16* xp = x + row * kD;
    const __nv_bfloat16* yp = y + row * kD;

    float v[4];
    float s = 0.f;
#pragma unroll
    for (int i = 0; i < 4; i++) {
        const int idx = threadIdx.x + (i << 8);
        v[i] = __bfloat162float(xp[idx]) + __bfloat162float(yp[idx]);
        s += v[i];
    }
    s = block_sum(s, sh);
    const float mean = s * (1.f / kD);
    float sq = 0.f;
#pragma unroll
    for (int i = 0; i < 4; i++) { const float d = v[i] - mean; sq += d * d; }
    sq = block_sum(sq, sh);
    const float r = rsqrtf(sq * (1.f / kD) + kLnEps);
#pragma unroll
    for (int i = 0; i < 4; i++) {
        const int idx = threadIdx.x + (i << 8);
        xp[idx] = __float2bfloat16_rn((v[i] - mean) * r * gamma[idx] + beta[idx]);
    }
}

// ---------------------------------------------------------------------------
// Row squared-L2 norms (bf16 in, fp32 out)
// ---------------------------------------------------------------------------
__global__ void rownorm_kernel(const __nv_bfloat16* __restrict__ x, float* __restrict__ out)
{
    __shared__ float sh[8];
    const long long row = blockIdx.x;
    const __nv_bfloat16* xp = x + row * kD;
    float s = 0.f;
#pragma unroll
    for (int i = 0; i < 4; i++) {
        const float v = __bfloat162float(xp[threadIdx.x + (i << 8)]);
        s += v * v;
    }
    s = block_sum(s, sh);
    if (threadIdx.x == 0) out[row] = s;
}

// ---------------------------------------------------------------------------
// dist + mask + log_softmax over T (in-place on fp32 cross buffer)
// ---------------------------------------------------------------------------
__global__ void dist_logsoftmax_kernel(float* __restrict__ out,
                                       const float* __restrict__ un,
                                       const float* __restrict__ tn,
                                       const int* __restrict__ pad_u,
                                       const int* __restrict__ pad_t)
{
    __shared__ float sh[8];
    const int row = blockIdx.x;
    const int b = row / kU;
    float* p = out + (long long)row * kT;
    const int t = threadIdx.x;

    const bool masked = (pad_u[row] != 0) || (pad_t[b * kT + t] != 0);
    const float v = masked ? kNeg
                           : -kTemp * (un[row] + tn[b * kT + t] - 2.f * p[t]);
    const float m = block_max(v, sh);
    const float e = __expf(v - m);
    const float s = block_sum(e, sh);
    p[t] = v - m - logf(s);
}

// ---------------------------------------------------------------------------
// Host orchestration
// ---------------------------------------------------------------------------
namespace {

constexpr size_t kGemmSmem = 4 * 256 * 80;  // 81920 bytes

struct EncParams {
    const float *emb, *ipb, *ob, *l1s, *l1b, *f1b, *f2b, *l2s, *l2b;
    const __nv_bfloat16 *ipw, *ow, *f1w, *f2w;  // bf16 copies
};

void run_encoder(const int* tokens, int Slen, int padidx, const EncParams& P,
                 __nv_bfloat16* x, int* pad, __nv_bfloat16* qkv, float* scores,
                 __nv_bfloat16* probs, __nv_bfloat16* att, __nv_bfloat16* tmp,
                 __nv_bfloat16* ffb, __nv_bfloat16* vt)
{
    const int Ntok = kB * Slen;
    embed_kernel<<<Ntok, 256>>>(tokens, P.emb, x, pad, padidx);

    for (int l = 0; l < kL; l++) {
        const __nv_bfloat16* ipw = P.ipw + (long long)l * 3 * kD * kD;
        const __nv_bfloat16* ow  = P.ow  + (long long)l * kD * kD;
        const __nv_bfloat16* f1w = P.f1w + (long long)l * kFF * kD;
        const __nv_bfloat16* f2w = P.f2w + (long long)l * kD * kFF;
        const float* ipb = P.ipb + (size_t)l * 3 * kD;
        const float* ob  = P.ob  + (size_t)l * kD;
        const float* l1s = P.l1s + (size_t)l * kD;
        const float* l1b = P.l1b + (size_t)l * kD;
        const float* f1b = P.f1b + (size_t)l * kFF;
        const float* f2b = P.f2b + (size_t)l * kD;
        const float* l2s = P.l2s + (size_t)l * kD;
        const float* l2b = P.l2b + (size_t)l * kD;

        // qkv = x @ ipw^T + ipb
        bf_gemm<__nv_bfloat16, false><<<dim3(3 * kD / 128, Ntok / 128, 1), 256, kGemmSmem>>>(
            x, ipw, ipb, qkv, kD, kD, kD, 3 * kD, 1, 0, 0, 0, 0, 0, 0);

        transpose_v<<<dim3(Slen / 32, 4, kB * kH), dim3(32, 8)>>>(qkv, vt, Slen);

        // scores[b,h] = Q @ K^T (fp32 out; scale applied in softmax)
        bf_gemm<float, false><<<dim3(Slen / 128, Slen / 128, kB * kH), 256, kGemmSmem>>>(
            qkv, qkv + kD, nullptr, scores, 128, 3 * kD, 3 * kD, Slen,
            kH,
            (long long)Slen * 3 * kD, 128LL,
            (long long)Slen * 3 * kD, 128LL,
            (long long)kH * Slen * Slen, (long long)Slen * Slen);

        attn_softmax_kernel<<<kB * kH * Slen, 256>>>(scores, probs, pad, Slen);

        // att[b,q,h*128+d] = probs[b,h] @ vt[b,h]^T
        bf_gemm<__nv_bfloat16, false><<<dim3(1, Slen / 128, kB * kH), 256, kGemmSmem>>>(
            probs, vt, nullptr, att, Slen, Slen, Slen, kD,
            kH,
            (long long)kH * Slen * Slen, (long long)Slen * Slen,
            (long long)kH * 128 * Slen, (long long)128 * Slen,
            (long long)Slen * kD, 128LL);

        // o = att @ ow^T + ob -> tmp
        bf_gemm<__nv_bfloat16, false><<<dim3(kD / 128, Ntok / 128, 1), 256, kGemmSmem>>>(
            att, ow, ob, tmp, kD, kD, kD, kD, 1, 0, 0, 0, 0, 0, 0);

        add_ln_kernel<<<Ntok, 256>>>(x, tmp, l1s, l1b);

        // h = relu(x @ f1w^T + f1b) -> ffb
        bf_gemm<__nv_bfloat16, true><<<dim3(kFF / 128, Ntok / 128, 1), 256, kGemmSmem>>>(
            x, f1w, f1b, ffb, kD, kD, kD, kFF, 1, 0, 0, 0, 0, 0, 0);

        // y = h @ f2w^T + f2b -> tmp
        bf_gemm<__nv_bfloat16, false><<<dim3(kD / 128, Ntok / 128, 1), 256, kGemmSmem>>>(
            ffb, f2w, f2b, tmp, kFF, kFF, kFF, kD, 1, 0, 0, 0, 0, 0, 0);

        add_ln_kernel<<<Ntok, 256>>>(x, tmp, l2s, l2b);
    }
}

}  // namespace

extern "C" void kernel_launch(void* const* d_in, const int* in_sizes, int n_in,
                              void* d_out, int out_size)
{
    (void)in_sizes; (void)n_in; (void)out_size;
    const int* text_tokens = (const int*)d_in[0];
    const int* unit_tokens = (const int*)d_in[1];
    auto f = [&](int i) { return (const float*)d_in[i]; };
    float* out = (float*)d_out;

    cudaFuncSetAttribute(bf_gemm<__nv_bfloat16, false>,
                         cudaFuncAttributeMaxDynamicSharedMemorySize, (int)kGemmSmem);
    cudaFuncSetAttribute(bf_gemm<__nv_bfloat16, true>,
                         cudaFuncAttributeMaxDynamicSharedMemorySize, (int)kGemmSmem);
    cudaFuncSetAttribute(bf_gemm<float, false>,
                         cudaFuncAttributeMaxDynamicSharedMemorySize, (int)kGemmSmem);

    __nv_bfloat16 *x_u, *x_t, *qkv, *probs, *att, *tmp, *ffb, *vt, *wbf;
    float *scores, *un, *tn;
    int *pad_u, *pad_t;
    cudaGetSymbolAddress((void**)&x_u, g_x_u);
    cudaGetSymbolAddress((void**)&x_t, g_x_t);
    cudaGetSymbolAddress((void**)&qkv, g_qkv);
    cudaGetSymbolAddress((void**)&scores, g_scores);
    cudaGetSymbolAddress((void**)&probs, g_probs);
    cudaGetSymbolAddress((void**)&att, g_att);
    cudaGetSymbolAddress((void**)&tmp, g_tmp);
    cudaGetSymbolAddress((void**)&ffb, g_ffb);
    cudaGetSymbolAddress((void**)&vt, g_vt);
    cudaGetSymbolAddress((void**)&wbf, g_wbf);
    cudaGetSymbolAddress((void**)&un, g_un);
    cudaGetSymbolAddress((void**)&tn, g_tn);
    cudaGetSymbolAddress((void**)&pad_u, g_pad_u);
    cudaGetSymbolAddress((void**)&pad_t, g_pad_t);

    // Convert weights fp32 -> bf16 (input order: t @ 2.., u @ 15..)
    // indices: emb,ipw,ipb,ow,ob,l1s,l1b,f1w,f1b,f2w,f2b,l2s,l2b
    for (int e = 0; e < 2; e++) {
        const int base = e == 0 ? 2 : 15;
        __nv_bfloat16* w = wbf + (long long)e * kWEnc;
        f2bf_kernel<<<(int)(kWipw / 1024), 256>>>(f(base + 1), w, (int)kWipw);
        f2bf_kernel<<<(int)(kWow / 1024), 256>>>(f(base + 3), w + kWipw, (int)kWow);
        f2bf_kernel<<<(int)(kWf1 / 1024), 256>>>(f(base + 7), w + kWipw + kWow, (int)kWf1);
        f2bf_kernel<<<(int)(kWf2 / 1024), 256>>>(f(base + 9), w + kWipw + kWow + kWf1, (int)kWf2);
    }

    EncParams tP, uP;
    {
        const __nv_bfloat16* w = wbf;
        tP = EncParams{f(2), f(4), f(6), f(7), f(8), f(10), f(12), f(13), f(14),
                       w, w + kWipw, w + kWipw + kWow, w + kWipw + kWow + kWf1};
        const __nv_bfloat16* w2 = wbf + kWEnc;
        uP = EncParams{f(15), f(17), f(19), f(20), f(21), f(23), f(25), f(26), f(27),
                       w2, w2 + kWipw, w2 + kWipw + kWow, w2 + kWipw + kWow + kWf1};
    }

    run_encoder(text_tokens, kT, kTextV - 1, tP, x_t, pad_t, qkv, scores, probs,
                att, tmp, ffb, vt);
    run_encoder(unit_tokens, kU, kUnitV - 1, uP, x_u, pad_u, qkv, scores, probs,
                att, tmp, ffb, vt);

    rownorm_kernel<<<kB * kU, 256>>>(x_u, un);
    rownorm_kernel<<<kB * kT, 256>>>(x_t, tn);

    // cross[b,u,t] = uf . tf (fp32 into out), batched over b
    bf_gemm<float, false><<<dim3(kT / 128, kU / 128, kB), 256, kGemmSmem>>>(
        x_u, x_t, nullptr, out, kD, kD, kD, kT,
        1, (long long)kU * kD, 0, (long long)kT * kD, 0,
        (long long)kU * kT, 0);

    dist_logsoftmax_kernel<<<kB * kU, 256>>>(out, un, tn, pad_u, pad_t);
}